// round 12
// baseline (speedup 1.0000x reference)
#include <cuda_runtime.h>
#include <math.h>

#define NNODES 65536
#define NEDGES 1048576
#define NG 512
#define ECAP 48   // per-dst capacity: Binomial(2048,1/128); P(any node >48) ~ 1e-10

// ---------------- device scratch (allocation-free: __device__ globals) -------
__device__ __align__(16) float         g_dinv[NNODES];
__device__ __align__(16) unsigned      g_cnt[NNODES];
__device__ __align__(16) unsigned      g_rowstart[NNODES + 1];
__device__ __align__(16) unsigned      g_fill[NNODES];
__device__ __align__(16) unsigned      g_bsum[256];
__device__ __align__(16) int           g_eid[NEDGES];
__device__ __align__(16) float         g_coef[(size_t)NNODES * ECAP];
__device__ __align__(16) unsigned char g_slocal[(size_t)NNODES * ECAP];
__device__ __align__(16) float         g_hcat[(size_t)NNODES * 256];

// ---------------- XLA f32 tanh: rational approx, NO FMA (XLA emits mul+add) ---
__device__ __forceinline__ float tanh_xla(float x) {
    const float kMax = 7.90531110763549805f;
    float ax = fabsf(x);
    float xc = fminf(fmaxf(x, -kMax), kMax);
    float x2 = __fmul_rn(xc, xc);
    float p = -2.76076847742355e-16f;
    p = __fadd_rn(__fmul_rn(p, x2),  2.00018790482477e-13f);
    p = __fadd_rn(__fmul_rn(p, x2), -8.60467152213735e-11f);
    p = __fadd_rn(__fmul_rn(p, x2),  5.12229709037114e-08f);
    p = __fadd_rn(__fmul_rn(p, x2),  1.48572235717979e-05f);
    p = __fadd_rn(__fmul_rn(p, x2),  6.37261928875436e-04f);
    p = __fadd_rn(__fmul_rn(p, x2),  4.89352455891786e-03f);
    p = __fmul_rn(xc, p);
    float q = 1.19825839466702e-06f;
    q = __fadd_rn(__fmul_rn(q, x2),  1.18534705686654e-04f);
    q = __fadd_rn(__fmul_rn(q, x2),  2.26843463243900e-03f);
    q = __fadd_rn(__fmul_rn(q, x2),  4.89352518554385e-03f);
    float r = __fdiv_rn(p, q);
    return (ax < 0.0004f) ? x : r;
}

// ---------------- degree counting / CSR build ---------------------------------
__global__ void k_zero_cnt() {
    int i = blockIdx.x * blockDim.x + threadIdx.x;
    if (i < NNODES) g_cnt[i] = 0u;
}
__global__ void k_count(const int* __restrict__ dst) {
    int e = blockIdx.x * blockDim.x + threadIdx.x;
    if (e < NEDGES) atomicAdd(&g_cnt[dst[e]], 1u);
}
__global__ void k_dinv() {
    int i = blockIdx.x * blockDim.x + threadIdx.x;
    if (i < NNODES) g_dinv[i] = rsqrtf((float)(g_cnt[i] + 1u));
}
__global__ void k_scan1() {
    __shared__ unsigned s[256];
    int t = threadIdx.x;
    int i = blockIdx.x * 256 + t;
    unsigned v = g_cnt[i];
    s[t] = v;
    __syncthreads();
    for (int off = 1; off < 256; off <<= 1) {
        unsigned u = (t >= off) ? s[t - off] : 0u;
        __syncthreads();
        s[t] += u;
        __syncthreads();
    }
    g_rowstart[i] = s[t] - v;
    if (t == 255) g_bsum[blockIdx.x] = s[255];
}
__global__ void k_scan2() {
    __shared__ unsigned s[256];
    int t = threadIdx.x;
    unsigned v = g_bsum[t];
    s[t] = v;
    __syncthreads();
    for (int off = 1; off < 256; off <<= 1) {
        unsigned u = (t >= off) ? s[t - off] : 0u;
        __syncthreads();
        s[t] += u;
        __syncthreads();
    }
    g_bsum[t] = s[t] - v;
}
__global__ void k_scan3() {
    int i = blockIdx.x * blockDim.x + threadIdx.x;
    if (i < NNODES) {
        unsigned r = g_rowstart[i] + g_bsum[i >> 8];
        g_rowstart[i] = r;
        g_fill[i] = r;
    }
    if (i == 0) g_rowstart[NNODES] = NEDGES;
}
__global__ void k_scatter(const int* __restrict__ dst) {
    int e = blockIdx.x * blockDim.x + threadIdx.x;
    if (e < NEDGES) {
        unsigned p = atomicAdd(&g_fill[dst[e]], 1u);
        g_eid[p] = e;
    }
}
// per-dst edge lists: ascending edge id (deterministic), coef + src-local
__global__ void k_edges(const int* __restrict__ srcArr) {
    int n = blockIdx.x * blockDim.x + threadIdx.x;
    if (n >= NNODES) return;
    int base = (int)g_rowstart[n];
    int cnt  = (int)g_rowstart[n + 1] - base;
    if (cnt > ECAP) cnt = ECAP;
    int ids[ECAP];
    for (int i = 0; i < cnt; i++) ids[i] = g_eid[base + i];
    for (int i = 1; i < cnt; i++) {
        int key = ids[i], j = i - 1;
        while (j >= 0 && ids[j] > key) { ids[j + 1] = ids[j]; j--; }
        ids[j + 1] = key;
    }
    float dvd = g_dinv[n];
    for (int i = 0; i < cnt; i++) {
        int s = srcArr[ids[i]];
        g_coef[(size_t)n * ECAP + i] = __fmul_rn(g_dinv[s], dvd);
        g_slocal[(size_t)n * ECAP + i] = (unsigned char)(s & 127);
    }
}

// ---------------- GCN layer body: one CTA per graph, PURE FP32 -----------------
// H = X@W with fp32 FMA chains (ascending k, Eigen-like), then fp32 edge
// aggregation in ascending-edge-id order, self-loop, bias, XLA tanh.
template <int CIN, int COUT, int COUTB>
__device__ __forceinline__ void gcn_body(
    const float* __restrict__ xin, int xstride, int xoff,
    const float* __restrict__ W, const float* __restrict__ b, int outoff)
{
    constexpr int HS = COUTB + 1;
    constexpr int NC = COUTB / 16;
    __shared__ float Hs[128 * HS];
    __shared__ float Xb[128 * 17];
    __shared__ float Wb[16 * COUTB];

    const int tid = threadIdx.x;
    const int ty  = tid >> 4;
    const int tx  = tid & 15;
    const int gbase = blockIdx.x << 7;

    for (int cb = 0; cb < COUT; cb += COUTB) {
        float acc[8][NC];
#pragma unroll
        for (int i = 0; i < 8; i++)
#pragma unroll
            for (int j = 0; j < NC; j++) acc[i][j] = 0.f;

        for (int kb = 0; kb < CIN; kb += 16) {
            for (int idx = tid; idx < 128 * 16; idx += 256) {
                int r = idx >> 4, c = idx & 15;
                Xb[r * 17 + c] = xin[(size_t)(gbase + r) * xstride + xoff + kb + c];
            }
            for (int idx = tid; idx < 16 * COUTB; idx += 256) {
                int k = idx / COUTB, c = idx - k * COUTB;
                Wb[k * COUTB + c] = W[(size_t)(kb + k) * COUT + cb + c];
            }
            __syncthreads();
#pragma unroll
            for (int k = 0; k < 16; k++) {
                float a[8], bb[NC];
#pragma unroll
                for (int i = 0; i < 8; i++) a[i] = Xb[(ty + i * 16) * 17 + k];
#pragma unroll
                for (int j = 0; j < NC; j++) bb[j] = Wb[k * COUTB + tx + j * 16];
#pragma unroll
                for (int i = 0; i < 8; i++)
#pragma unroll
                    for (int j = 0; j < NC; j++) acc[i][j] = fmaf(a[i], bb[j], acc[i][j]);
            }
            __syncthreads();
        }
#pragma unroll
        for (int i = 0; i < 8; i++)
#pragma unroll
            for (int j = 0; j < NC; j++)
                Hs[(ty + i * 16) * HS + tx + j * 16] = acc[i][j];
        __syncthreads();

        // ---- aggregation: 2 threads per dst, COUTB/2 channels each (fp32) ----
        {
            const int d = tid >> 1, half = tid & 1;
            const int n = gbase + d;
            int cnt = (int)g_rowstart[n + 1] - (int)g_rowstart[n];
            if (cnt > ECAP) cnt = ECAP;
            const float dvd = g_dinv[n];
            const float sl2 = __fmul_rn(dvd, dvd);
            const int cb0 = half * (COUTB / 2);
            float accv[COUTB / 2];
#pragma unroll
            for (int c = 0; c < COUTB / 2; c++) accv[c] = 0.f;
            const float* cfp = g_coef + (size_t)n * ECAP;
            const unsigned char* slp = g_slocal + (size_t)n * ECAP;
            for (int i = 0; i < cnt; i++) {
                float cf = cfp[i];
                int s = (int)slp[i];
#pragma unroll
                for (int c = 0; c < COUTB / 2; c++)
                    accv[c] = __fadd_rn(accv[c], __fmul_rn(Hs[s * HS + cb0 + c], cf));
            }
#pragma unroll
            for (int c = 0; c < COUTB / 2; c++) {
                float sl = __fmul_rn(Hs[d * HS + cb0 + c], sl2);
                float v  = __fadd_rn(accv[c], sl);
                v = __fadd_rn(v, __ldg(&b[cb + cb0 + c]));
                g_hcat[(size_t)n * 256 + outoff + cb + cb0 + c] = tanh_xla(v);
            }
        }
        __syncthreads();
    }
}

__global__ __launch_bounds__(256) void k_gcn1(const float* __restrict__ x,
        const float* __restrict__ W, const float* __restrict__ b)
{ gcn_body<128, 128, 64>(x, 128, 0, W, b, 0); }
__global__ __launch_bounds__(256) void k_gcn2(const float* __restrict__ W,
        const float* __restrict__ b)
{ gcn_body<128, 64, 64>(g_hcat, 256, 0, W, b, 128); }
__global__ __launch_bounds__(256) void k_gcn3(const float* __restrict__ W,
        const float* __restrict__ b)
{ gcn_body<64, 32, 32>(g_hcat, 256, 128, W, b, 192); }
__global__ __launch_bounds__(256) void k_gcn4(const float* __restrict__ W,
        const float* __restrict__ b)
{ gcn_body<32, 32, 32>(g_hcat, 256, 192, W, b, 224); }

// ---------------- fused head (static smem ~38KB), PURE FP32 --------------------
__global__ __launch_bounds__(256) void k_head(
    const float* __restrict__ W5, const float* __restrict__ b5,
    const float* __restrict__ W6, const float* __restrict__ b6,
    const float* __restrict__ Wf1, const float* __restrict__ bf1,
    const float* __restrict__ Wf2, const float* __restrict__ bf2,
    float* __restrict__ out)
{
    __shared__ float W5s[4096];
    __shared__ float W6s[2560];
    __shared__ float vals[128];
    __shared__ int   order[64];
    __shared__ float z[16 * 64];
    __shared__ float zp[16 * 32];
    __shared__ float y[896];
    __shared__ float f1[128];
    __shared__ float logits[10];
    __shared__ float red[2];

    const int g = blockIdx.x, tid = threadIdx.x;
    const float* hrow = g_hcat + (size_t)g * 128 * 256;

    if (tid < 128) vals[tid] = hrow[tid * 256 + 255];
    for (int i = tid; i < 4096; i += 256) W5s[i] = W5[i];
    for (int i = tid; i < 2560; i += 256) W6s[i] = W6[i];
    __syncthreads();

    // stable descending rank (matches stable jnp.argsort(-v): ties -> lower idx)
    if (tid < 128) {
        float v = vals[tid];
        int rank = 0;
        for (int j = 0; j < 128; j++) {
            float vj = vals[j];
            rank += (vj > v) || (vj == v && j < tid);
        }
        if (rank < 64) order[rank] = tid;
    }
    __syncthreads();

    // Conv1d(1,16,256,256): z[c][t] = relu(pooled[t].W5[c] + b5[c])
    {
        int c = tid >> 4, tg = tid & 15;
        float bc = b5[c];
#pragma unroll
        for (int m = 0; m < 4; m++) {
            int t = tg + 16 * m;
            const float* row = hrow + (size_t)order[t] * 256;
            float a0 = 0.f;
#pragma unroll 4
            for (int j = 0; j < 256; j++)
                a0 = fmaf(__ldg(row + j), W5s[c * 256 + j], a0);
            z[c * 64 + t] = fmaxf(__fadd_rn(a0, bc), 0.f);
        }
    }
    __syncthreads();

    // MaxPool1d(2,2)
    for (int idx = tid; idx < 512; idx += 256) {
        int c = idx >> 5, u = idx & 31;
        zp[c * 32 + u] = fmaxf(z[c * 64 + 2 * u], z[c * 64 + 2 * u + 1]);
    }
    __syncthreads();

    // Conv1d(16,32,5) VALID + relu
    for (int idx = tid; idx < 896; idx += 256) {
        int o = idx / 28, t = idx - o * 28;
        float a0 = 0.f;
#pragma unroll
        for (int i = 0; i < 16; i++)
#pragma unroll
            for (int k = 0; k < 5; k++)
                a0 = fmaf(zp[i * 32 + t + k], W6s[(o * 16 + i) * 5 + k], a0);
        y[idx] = fmaxf(__fadd_rn(a0, b6[o]), 0.f);
    }
    __syncthreads();

    // FC1 896->128 relu
    if (tid < 128) {
        float a0 = 0.f;
#pragma unroll 8
        for (int i = 0; i < 896; i++)
            a0 = fmaf(y[i], __ldg(&Wf1[(size_t)i * 128 + tid]), a0);
        f1[tid] = fmaxf(__fadd_rn(a0, bf1[tid]), 0.f);
    }
    __syncthreads();

    // FC2 128->10
    if (tid < 10) {
        float a0 = 0.f;
#pragma unroll 8
        for (int j = 0; j < 128; j++)
            a0 = fmaf(f1[j], __ldg(&Wf2[j * 10 + tid]), a0);
        logits[tid] = __fadd_rn(a0, bf2[tid]);
    }
    __syncthreads();
    if (tid == 0) {
        float m = logits[0];
        for (int k = 1; k < 10; k++) m = fmaxf(m, logits[k]);
        float s = 0.f;
        for (int k = 0; k < 10; k++) s += expf(logits[k] - m);
        red[0] = m;
        red[1] = logf(s);
    }
    __syncthreads();
    if (tid < 10) out[g * 10 + tid] = logits[tid] - red[0] - red[1];
}

// ---------------- launch (no dynamic smem, no attributes) -----------------------
extern "C" void kernel_launch(void* const* d_in, const int* in_sizes, int n_in,
                              void* d_out, int out_size)
{
    const float* x   = (const float*)d_in[0];
    const float* W1  = (const float*)d_in[1];
    const float* b1  = (const float*)d_in[2];
    const float* W2  = (const float*)d_in[3];
    const float* b2  = (const float*)d_in[4];
    const float* W3  = (const float*)d_in[5];
    const float* b3  = (const float*)d_in[6];
    const float* W4  = (const float*)d_in[7];
    const float* b4  = (const float*)d_in[8];
    const float* W5  = (const float*)d_in[9];
    const float* b5  = (const float*)d_in[10];
    const float* W6  = (const float*)d_in[11];
    const float* b6  = (const float*)d_in[12];
    const float* Wf1 = (const float*)d_in[13];
    const float* bf1 = (const float*)d_in[14];
    const float* Wf2 = (const float*)d_in[15];
    const float* bf2 = (const float*)d_in[16];
    const int*   ei  = (const int*)d_in[17];
    const int* src = ei;
    const int* dst = ei + NEDGES;
    float* out = (float*)d_out;

    // degree + CSR + deterministic per-dst edge lists
    k_zero_cnt<<<NNODES / 256, 256>>>();
    k_count<<<NEDGES / 256, 256>>>(dst);
    k_dinv<<<NNODES / 256, 256>>>();
    k_scan1<<<256, 256>>>();
    k_scan2<<<1, 256>>>();
    k_scan3<<<NNODES / 256, 256>>>();
    k_scatter<<<NEDGES / 256, 256>>>(dst);
    k_edges<<<NNODES / 256, 256>>>(src);

    // GCN layers -> concat buffer columns 0,128,192,224
    k_gcn1<<<NG, 256>>>(x, W1, b1);
    k_gcn2<<<NG, 256>>>(W2, b2);
    k_gcn3<<<NG, 256>>>(W3, b3);
    k_gcn4<<<NG, 256>>>(W4, b4);

    // sort-pool + convs + MLP + log_softmax
    k_head<<<NG, 256>>>(W5, b5, W6, b6, Wf1, bf1, Wf2, bf2, out);
}

// round 13
// speedup vs baseline: 1.1606x; 1.1606x over previous
#include <cuda_runtime.h>
#include <math.h>

#define NNODES 65536
#define NEDGES 1048576
#define NG 512
#define ECAP 48   // per-dst capacity: Binomial(2048,1/128); P(any node >48) ~ 1e-10

// ---------------- device scratch (allocation-free: __device__ globals) -------
__device__ __align__(16) float         g_dinv[NNODES];
__device__ __align__(16) unsigned      g_cnt[NNODES];
__device__ __align__(16) unsigned      g_rowstart[NNODES + 1];
__device__ __align__(16) unsigned      g_fill[NNODES];
__device__ __align__(16) unsigned      g_bsum[256];
__device__ __align__(16) int           g_eid[NEDGES];
__device__ __align__(16) float         g_coef[(size_t)NNODES * ECAP];
__device__ __align__(16) unsigned char g_slocal[(size_t)NNODES * ECAP];
__device__ __align__(16) float         g_hcat[(size_t)NNODES * 256];

// ---------------- XLA f32 tanh: rational approx, NO FMA (XLA emits mul+add) ---
__device__ __forceinline__ float tanh_xla(float x) {
    const float kMax = 7.90531110763549805f;
    float ax = fabsf(x);
    float xc = fminf(fmaxf(x, -kMax), kMax);
    float x2 = __fmul_rn(xc, xc);
    float p = -2.76076847742355e-16f;
    p = __fadd_rn(__fmul_rn(p, x2),  2.00018790482477e-13f);
    p = __fadd_rn(__fmul_rn(p, x2), -8.60467152213735e-11f);
    p = __fadd_rn(__fmul_rn(p, x2),  5.12229709037114e-08f);
    p = __fadd_rn(__fmul_rn(p, x2),  1.48572235717979e-05f);
    p = __fadd_rn(__fmul_rn(p, x2),  6.37261928875436e-04f);
    p = __fadd_rn(__fmul_rn(p, x2),  4.89352455891786e-03f);
    p = __fmul_rn(xc, p);
    float q = 1.19825839466702e-06f;
    q = __fadd_rn(__fmul_rn(q, x2),  1.18534705686654e-04f);
    q = __fadd_rn(__fmul_rn(q, x2),  2.26843463243900e-03f);
    q = __fadd_rn(__fmul_rn(q, x2),  4.89352518554385e-03f);
    float r = __fdiv_rn(p, q);
    return (ax < 0.0004f) ? x : r;
}

// ---------------- degree counting / CSR build ---------------------------------
__global__ void k_zero_cnt() {
    int i = blockIdx.x * blockDim.x + threadIdx.x;
    if (i < NNODES) g_cnt[i] = 0u;
}
__global__ void k_count(const int* __restrict__ dst) {
    int e = blockIdx.x * blockDim.x + threadIdx.x;
    if (e < NEDGES) atomicAdd(&g_cnt[dst[e]], 1u);
}
__global__ void k_dinv() {
    int i = blockIdx.x * blockDim.x + threadIdx.x;
    if (i < NNODES) g_dinv[i] = rsqrtf((float)(g_cnt[i] + 1u));
}
__global__ void k_scan1() {
    __shared__ unsigned s[256];
    int t = threadIdx.x;
    int i = blockIdx.x * 256 + t;
    unsigned v = g_cnt[i];
    s[t] = v;
    __syncthreads();
    for (int off = 1; off < 256; off <<= 1) {
        unsigned u = (t >= off) ? s[t - off] : 0u;
        __syncthreads();
        s[t] += u;
        __syncthreads();
    }
    g_rowstart[i] = s[t] - v;
    if (t == 255) g_bsum[blockIdx.x] = s[255];
}
__global__ void k_scan2() {
    __shared__ unsigned s[256];
    int t = threadIdx.x;
    unsigned v = g_bsum[t];
    s[t] = v;
    __syncthreads();
    for (int off = 1; off < 256; off <<= 1) {
        unsigned u = (t >= off) ? s[t - off] : 0u;
        __syncthreads();
        s[t] += u;
        __syncthreads();
    }
    g_bsum[t] = s[t] - v;
}
__global__ void k_scan3() {
    int i = blockIdx.x * blockDim.x + threadIdx.x;
    if (i < NNODES) {
        unsigned r = g_rowstart[i] + g_bsum[i >> 8];
        g_rowstart[i] = r;
        g_fill[i] = r;
    }
    if (i == 0) g_rowstart[NNODES] = NEDGES;
}
__global__ void k_scatter(const int* __restrict__ dst) {
    int e = blockIdx.x * blockDim.x + threadIdx.x;
    if (e < NEDGES) {
        unsigned p = atomicAdd(&g_fill[dst[e]], 1u);
        g_eid[p] = e;
    }
}
// per-dst edge lists: ascending edge id (deterministic), coef + src-local
__global__ void k_edges(const int* __restrict__ srcArr) {
    int n = blockIdx.x * blockDim.x + threadIdx.x;
    if (n >= NNODES) return;
    int base = (int)g_rowstart[n];
    int cnt  = (int)g_rowstart[n + 1] - base;
    if (cnt > ECAP) cnt = ECAP;
    int ids[ECAP];
    for (int i = 0; i < cnt; i++) ids[i] = g_eid[base + i];
    for (int i = 1; i < cnt; i++) {
        int key = ids[i], j = i - 1;
        while (j >= 0 && ids[j] > key) { ids[j + 1] = ids[j]; j--; }
        ids[j + 1] = key;
    }
    float dvd = g_dinv[n];
    for (int i = 0; i < cnt; i++) {
        int s = srcArr[ids[i]];
        g_coef[(size_t)n * ECAP + i] = __fmul_rn(g_dinv[s], dvd);
        g_slocal[(size_t)n * ECAP + i] = (unsigned char)(s & 127);
    }
}

// ---------------- GCN layer body: one CTA per (graph, channel-block) -----------
// PURE FP32. GEMM: fp32 FMA chains (ascending k). Aggregation: WARP-PER-DST,
// lanes = channels -> conflict-free LDS, zero divergence, coalesced stores.
// Per-(n,c) arithmetic order identical to the passing R12 kernel (bitwise).
template <int CIN, int COUT, int COUTB>
__device__ __forceinline__ void gcn_body(
    const float* __restrict__ xin, int xstride, int xoff,
    const float* __restrict__ W, const float* __restrict__ b, int outoff)
{
    constexpr int HS = COUTB + 1;
    constexpr int NC = COUTB / 16;
    __shared__ float Hs[128 * HS];
    __shared__ float Xb[128 * 17];
    __shared__ float Wb[16 * COUTB];

    const int tid = threadIdx.x;
    const int ty  = tid >> 4;
    const int tx  = tid & 15;
    const int gbase = blockIdx.x << 7;
    const int cb    = blockIdx.y * COUTB;

    // ---- GEMM: H(:, cb:cb+COUTB) = X @ W(:, cb:cb+COUTB) ----
    float acc[8][NC];
#pragma unroll
    for (int i = 0; i < 8; i++)
#pragma unroll
        for (int j = 0; j < NC; j++) acc[i][j] = 0.f;

    for (int kb = 0; kb < CIN; kb += 16) {
        for (int idx = tid; idx < 128 * 16; idx += 256) {
            int r = idx >> 4, c = idx & 15;
            Xb[r * 17 + c] = xin[(size_t)(gbase + r) * xstride + xoff + kb + c];
        }
        for (int idx = tid; idx < 16 * COUTB; idx += 256) {
            int k = idx / COUTB, c = idx - k * COUTB;
            Wb[k * COUTB + c] = W[(size_t)(kb + k) * COUT + cb + c];
        }
        __syncthreads();
#pragma unroll
        for (int k = 0; k < 16; k++) {
            float a[8], bb[NC];
#pragma unroll
            for (int i = 0; i < 8; i++) a[i] = Xb[(ty + i * 16) * 17 + k];
#pragma unroll
            for (int j = 0; j < NC; j++) bb[j] = Wb[k * COUTB + tx + j * 16];
#pragma unroll
            for (int i = 0; i < 8; i++)
#pragma unroll
                for (int j = 0; j < NC; j++) acc[i][j] = fmaf(a[i], bb[j], acc[i][j]);
        }
        __syncthreads();
    }
#pragma unroll
    for (int i = 0; i < 8; i++)
#pragma unroll
        for (int j = 0; j < NC; j++)
            Hs[(ty + i * 16) * HS + tx + j * 16] = acc[i][j];
    __syncthreads();

    // ---- aggregation: warp per dst, lanes = channels ----
    {
        const int warp = tid >> 5, lane = tid & 31;
#pragma unroll 1
        for (int dd = 0; dd < 16; dd++) {
            const int d = warp * 16 + dd;
            const int n = gbase + d;
            int cnt = (int)g_rowstart[n + 1] - (int)g_rowstart[n];
            if (cnt > ECAP) cnt = ECAP;
            const float dvd = g_dinv[n];
            const float sl2 = __fmul_rn(dvd, dvd);
            const float* cfp = g_coef + (size_t)n * ECAP;
            const unsigned char* slp = g_slocal + (size_t)n * ECAP;
            float acc0 = 0.f, acc1 = 0.f;
            for (int i = 0; i < cnt; i++) {
                float cf = __ldg(cfp + i);          // warp-broadcast
                int   s  = (int)__ldg(slp + i);     // warp-broadcast
                acc0 = __fadd_rn(acc0, __fmul_rn(Hs[s * HS + lane], cf));
                if (COUTB == 64)
                    acc1 = __fadd_rn(acc1, __fmul_rn(Hs[s * HS + 32 + lane], cf));
            }
            {
                float v = __fadd_rn(acc0, __fmul_rn(Hs[d * HS + lane], sl2));
                v = __fadd_rn(v, __ldg(&b[cb + lane]));
                g_hcat[(size_t)n * 256 + outoff + cb + lane] = tanh_xla(v);
            }
            if (COUTB == 64) {
                float v = __fadd_rn(acc1, __fmul_rn(Hs[d * HS + 32 + lane], sl2));
                v = __fadd_rn(v, __ldg(&b[cb + 32 + lane]));
                g_hcat[(size_t)n * 256 + outoff + cb + 32 + lane] = tanh_xla(v);
            }
        }
    }
}

__global__ __launch_bounds__(256) void k_gcn1(const float* __restrict__ x,
        const float* __restrict__ W, const float* __restrict__ b)
{ gcn_body<128, 128, 64>(x, 128, 0, W, b, 0); }
__global__ __launch_bounds__(256) void k_gcn2(const float* __restrict__ W,
        const float* __restrict__ b)
{ gcn_body<128, 64, 64>(g_hcat, 256, 0, W, b, 128); }
__global__ __launch_bounds__(256) void k_gcn3(const float* __restrict__ W,
        const float* __restrict__ b)
{ gcn_body<64, 32, 32>(g_hcat, 256, 128, W, b, 192); }
__global__ __launch_bounds__(256) void k_gcn4(const float* __restrict__ W,
        const float* __restrict__ b)
{ gcn_body<32, 32, 32>(g_hcat, 256, 192, W, b, 224); }

// ---------------- fused head (static smem ~38KB), PURE FP32 --------------------
__global__ __launch_bounds__(256) void k_head(
    const float* __restrict__ W5, const float* __restrict__ b5,
    const float* __restrict__ W6, const float* __restrict__ b6,
    const float* __restrict__ Wf1, const float* __restrict__ bf1,
    const float* __restrict__ Wf2, const float* __restrict__ bf2,
    float* __restrict__ out)
{
    __shared__ float W5s[4096];
    __shared__ float W6s[2560];
    __shared__ float vals[128];
    __shared__ int   order[64];
    __shared__ float z[16 * 64];
    __shared__ float zp[16 * 32];
    __shared__ float y[896];
    __shared__ float f1[128];
    __shared__ float logits[10];
    __shared__ float red[2];

    const int g = blockIdx.x, tid = threadIdx.x;
    const float* hrow = g_hcat + (size_t)g * 128 * 256;

    if (tid < 128) vals[tid] = hrow[tid * 256 + 255];
    for (int i = tid; i < 4096; i += 256) W5s[i] = W5[i];
    for (int i = tid; i < 2560; i += 256) W6s[i] = W6[i];
    __syncthreads();

    // stable descending rank (matches stable jnp.argsort(-v): ties -> lower idx)
    if (tid < 128) {
        float v = vals[tid];
        int rank = 0;
        for (int j = 0; j < 128; j++) {
            float vj = vals[j];
            rank += (vj > v) || (vj == v && j < tid);
        }
        if (rank < 64) order[rank] = tid;
    }
    __syncthreads();

    // Conv1d(1,16,256,256): z[c][t] = relu(pooled[t].W5[c] + b5[c])
    {
        int c = tid >> 4, tg = tid & 15;
        float bc = b5[c];
#pragma unroll
        for (int m = 0; m < 4; m++) {
            int t = tg + 16 * m;
            const float* row = hrow + (size_t)order[t] * 256;
            float a0 = 0.f;
#pragma unroll 4
            for (int j = 0; j < 256; j++)
                a0 = fmaf(__ldg(row + j), W5s[c * 256 + j], a0);
            z[c * 64 + t] = fmaxf(__fadd_rn(a0, bc), 0.f);
        }
    }
    __syncthreads();

    // MaxPool1d(2,2)
    for (int idx = tid; idx < 512; idx += 256) {
        int c = idx >> 5, u = idx & 31;
        zp[c * 32 + u] = fmaxf(z[c * 64 + 2 * u], z[c * 64 + 2 * u + 1]);
    }
    __syncthreads();

    // Conv1d(16,32,5) VALID + relu
    for (int idx = tid; idx < 896; idx += 256) {
        int o = idx / 28, t = idx - o * 28;
        float a0 = 0.f;
#pragma unroll
        for (int i = 0; i < 16; i++)
#pragma unroll
            for (int k = 0; k < 5; k++)
                a0 = fmaf(zp[i * 32 + t + k], W6s[(o * 16 + i) * 5 + k], a0);
        y[idx] = fmaxf(__fadd_rn(a0, b6[o]), 0.f);
    }
    __syncthreads();

    // FC1 896->128 relu
    if (tid < 128) {
        float a0 = 0.f;
#pragma unroll 8
        for (int i = 0; i < 896; i++)
            a0 = fmaf(y[i], __ldg(&Wf1[(size_t)i * 128 + tid]), a0);
        f1[tid] = fmaxf(__fadd_rn(a0, bf1[tid]), 0.f);
    }
    __syncthreads();

    // FC2 128->10
    if (tid < 10) {
        float a0 = 0.f;
#pragma unroll 8
        for (int j = 0; j < 128; j++)
            a0 = fmaf(f1[j], __ldg(&Wf2[j * 10 + tid]), a0);
        logits[tid] = __fadd_rn(a0, bf2[tid]);
    }
    __syncthreads();
    if (tid == 0) {
        float m = logits[0];
        for (int k = 1; k < 10; k++) m = fmaxf(m, logits[k]);
        float s = 0.f;
        for (int k = 0; k < 10; k++) s += expf(logits[k] - m);
        red[0] = m;
        red[1] = logf(s);
    }
    __syncthreads();
    if (tid < 10) out[g * 10 + tid] = logits[tid] - red[0] - red[1];
}

// ---------------- launch (no dynamic smem, no attributes) -----------------------
extern "C" void kernel_launch(void* const* d_in, const int* in_sizes, int n_in,
                              void* d_out, int out_size)
{
    const float* x   = (const float*)d_in[0];
    const float* W1  = (const float*)d_in[1];
    const float* b1  = (const float*)d_in[2];
    const float* W2  = (const float*)d_in[3];
    const float* b2  = (const float*)d_in[4];
    const float* W3  = (const float*)d_in[5];
    const float* b3  = (const float*)d_in[6];
    const float* W4  = (const float*)d_in[7];
    const float* b4  = (const float*)d_in[8];
    const float* W5  = (const float*)d_in[9];
    const float* b5  = (const float*)d_in[10];
    const float* W6  = (const float*)d_in[11];
    const float* b6  = (const float*)d_in[12];
    const float* Wf1 = (const float*)d_in[13];
    const float* bf1 = (const float*)d_in[14];
    const float* Wf2 = (const float*)d_in[15];
    const float* bf2 = (const float*)d_in[16];
    const int*   ei  = (const int*)d_in[17];
    const int* src = ei;
    const int* dst = ei + NEDGES;
    float* out = (float*)d_out;

    // degree + CSR + deterministic per-dst edge lists
    k_zero_cnt<<<NNODES / 256, 256>>>();
    k_count<<<NEDGES / 256, 256>>>(dst);
    k_dinv<<<NNODES / 256, 256>>>();
    k_scan1<<<256, 256>>>();
    k_scan2<<<1, 256>>>();
    k_scan3<<<NNODES / 256, 256>>>();
    k_scatter<<<NEDGES / 256, 256>>>(dst);
    k_edges<<<NNODES / 256, 256>>>(src);

    // GCN layers -> concat buffer columns 0,128,192,224
    k_gcn1<<<dim3(NG, 2), 256>>>(x, W1, b1);
    k_gcn2<<<dim3(NG, 1), 256>>>(W2, b2);
    k_gcn3<<<dim3(NG, 1), 256>>>(W3, b3);
    k_gcn4<<<dim3(NG, 1), 256>>>(W4, b4);

    // sort-pool + convs + MLP + log_softmax
    k_head<<<NG, 256>>>(W5, b5, W6, b6, Wf1, bf1, Wf2, bf2, out);
}

// round 14
// speedup vs baseline: 1.7519x; 1.5095x over previous
#include <cuda_runtime.h>
#include <math.h>

#define NNODES 65536
#define NEDGES 1048576
#define NG 512
#define ECAP 48   // per-dst capacity: Binomial(2048,1/128); P(any node >48) ~ 1e-10

// ---------------- device scratch (allocation-free: __device__ globals) -------
__device__ __align__(16) float    g_dinv[NNODES];
__device__ __align__(16) unsigned g_cnt[NNODES];
__device__ __align__(16) unsigned g_rowstart[NNODES + 1];
__device__ __align__(16) unsigned g_fill[NNODES];
__device__ __align__(16) unsigned g_bsum[256];
__device__ __align__(16) int      g_eid[NEDGES];
__device__ __align__(16) int2     g_cs[(size_t)NNODES * ECAP];   // {coef bits, slocal}
__device__ __align__(16) float    g_hcat[(size_t)NNODES * 256];

// ---------------- packed f32x2 helpers (bitwise = two scalar fp32 FMAs) -------
__device__ __forceinline__ unsigned long long pack2(float lo, float hi) {
    unsigned long long r;
    asm("mov.b64 %0, {%1,%2};" : "=l"(r) : "f"(lo), "f"(hi));
    return r;
}
__device__ __forceinline__ void unpack2(float& lo, float& hi, unsigned long long v) {
    asm("mov.b64 {%0,%1}, %2;" : "=f"(lo), "=f"(hi) : "l"(v));
}
__device__ __forceinline__ void ffma2(unsigned long long& d,
                                      unsigned long long a, unsigned long long b) {
    asm("fma.rn.f32x2 %0, %1, %2, %0;" : "+l"(d) : "l"(a), "l"(b));
}

// ---------------- XLA f32 tanh: rational approx, NO FMA (XLA emits mul+add) ---
__device__ __forceinline__ float tanh_xla(float x) {
    const float kMax = 7.90531110763549805f;
    float ax = fabsf(x);
    float xc = fminf(fmaxf(x, -kMax), kMax);
    float x2 = __fmul_rn(xc, xc);
    float p = -2.76076847742355e-16f;
    p = __fadd_rn(__fmul_rn(p, x2),  2.00018790482477e-13f);
    p = __fadd_rn(__fmul_rn(p, x2), -8.60467152213735e-11f);
    p = __fadd_rn(__fmul_rn(p, x2),  5.12229709037114e-08f);
    p = __fadd_rn(__fmul_rn(p, x2),  1.48572235717979e-05f);
    p = __fadd_rn(__fmul_rn(p, x2),  6.37261928875436e-04f);
    p = __fadd_rn(__fmul_rn(p, x2),  4.89352455891786e-03f);
    p = __fmul_rn(xc, p);
    float q = 1.19825839466702e-06f;
    q = __fadd_rn(__fmul_rn(q, x2),  1.18534705686654e-04f);
    q = __fadd_rn(__fmul_rn(q, x2),  2.26843463243900e-03f);
    q = __fadd_rn(__fmul_rn(q, x2),  4.89352518554385e-03f);
    float r = __fdiv_rn(p, q);
    return (ax < 0.0004f) ? x : r;
}

// ---------------- degree counting / CSR build ---------------------------------
__global__ void k_zero_cnt() {
    int i = blockIdx.x * blockDim.x + threadIdx.x;
    if (i < NNODES) g_cnt[i] = 0u;
}
__global__ void k_count(const int* __restrict__ dst) {
    int e = blockIdx.x * blockDim.x + threadIdx.x;
    if (e < NEDGES) atomicAdd(&g_cnt[dst[e]], 1u);
}
// scan stage 1 + dinv fused
__global__ void k_scan1() {
    __shared__ unsigned s[256];
    int t = threadIdx.x;
    int i = blockIdx.x * 256 + t;
    unsigned v = g_cnt[i];
    g_dinv[i] = rsqrtf((float)(v + 1u));
    s[t] = v;
    __syncthreads();
    for (int off = 1; off < 256; off <<= 1) {
        unsigned u = (t >= off) ? s[t - off] : 0u;
        __syncthreads();
        s[t] += u;
        __syncthreads();
    }
    g_rowstart[i] = s[t] - v;
    if (t == 255) g_bsum[blockIdx.x] = s[255];
}
__global__ void k_scan2() {
    __shared__ unsigned s[256];
    int t = threadIdx.x;
    unsigned v = g_bsum[t];
    s[t] = v;
    __syncthreads();
    for (int off = 1; off < 256; off <<= 1) {
        unsigned u = (t >= off) ? s[t - off] : 0u;
        __syncthreads();
        s[t] += u;
        __syncthreads();
    }
    g_bsum[t] = s[t] - v;
}
__global__ void k_scan3() {
    int i = blockIdx.x * blockDim.x + threadIdx.x;
    if (i < NNODES) {
        unsigned r = g_rowstart[i] + g_bsum[i >> 8];
        g_rowstart[i] = r;
        g_fill[i] = r;
    }
    if (i == 0) g_rowstart[NNODES] = NEDGES;
}
__global__ void k_scatter(const int* __restrict__ dst) {
    int e = blockIdx.x * blockDim.x + threadIdx.x;
    if (e < NEDGES) {
        unsigned p = atomicAdd(&g_fill[dst[e]], 1u);
        g_eid[p] = e;
    }
}
// per-dst edge lists: ascending edge id (deterministic), packed {coef, slocal}
__global__ void k_edges(const int* __restrict__ srcArr) {
    int n = blockIdx.x * blockDim.x + threadIdx.x;
    if (n >= NNODES) return;
    int base = (int)g_rowstart[n];
    int cnt  = (int)g_rowstart[n + 1] - base;
    if (cnt > ECAP) cnt = ECAP;
    int ids[ECAP];
    for (int i = 0; i < cnt; i++) ids[i] = g_eid[base + i];
    for (int i = 1; i < cnt; i++) {
        int key = ids[i], j = i - 1;
        while (j >= 0 && ids[j] > key) { ids[j + 1] = ids[j]; j--; }
        ids[j + 1] = key;
    }
    float dvd = g_dinv[n];
    for (int i = 0; i < cnt; i++) {
        int s = srcArr[ids[i]];
        int2 rec;
        rec.x = __float_as_int(__fmul_rn(g_dinv[s], dvd));
        rec.y = s & 127;
        g_cs[(size_t)n * ECAP + i] = rec;
    }
}

// ---------------- GCN layer body: one CTA per (graph, channel-block) -----------
// PURE FP32. GEMM via packed fma.rn.f32x2 (two independent IEEE fp32 FMAs per
// instr; per-element ascending-k chain bitwise identical to scalar fmaf chain).
// Aggregation: warp-per-dst, lanes = channels; int2 records, 4x unrolled loads
// (update order still ascending edge id -> bitwise identical).
template <int CIN, int COUT, int COUTB>
__device__ __forceinline__ void gcn_body(
    const float* __restrict__ xin, int xstride, int xoff,
    const float* __restrict__ W, const float* __restrict__ b, int outoff)
{
    constexpr int HS = COUTB + 1;
    constexpr int NP = COUTB / 32;     // u64 col-pairs per row per thread
    __shared__ float Hs[128 * HS];
    __shared__ float Xb[128 * 17];
    __shared__ float Wb[16 * COUTB];

    const int tid = threadIdx.x;
    const int ty  = tid >> 4;
    const int tx  = tid & 15;
    const int gbase = blockIdx.x << 7;
    const int cb    = blockIdx.y * COUTB;

    // ---- GEMM: H(:, cb:cb+COUTB) = X @ W(:, cb:cb+COUTB) ----
    unsigned long long acc[8][NP];
#pragma unroll
    for (int i = 0; i < 8; i++)
#pragma unroll
        for (int p = 0; p < NP; p++) acc[i][p] = 0ull;

    for (int kb = 0; kb < CIN; kb += 16) {
        for (int idx = tid; idx < 128 * 16; idx += 256) {
            int r = idx >> 4, c = idx & 15;
            Xb[r * 17 + c] = xin[(size_t)(gbase + r) * xstride + xoff + kb + c];
        }
        for (int idx = tid; idx < 16 * COUTB; idx += 256) {
            int k = idx / COUTB, c = idx - k * COUTB;
            Wb[k * COUTB + c] = W[(size_t)(kb + k) * COUT + cb + c];
        }
        __syncthreads();
#pragma unroll
        for (int k = 0; k < 16; k++) {
            unsigned long long bp[NP];
#pragma unroll
            for (int p = 0; p < NP; p++)
                bp[p] = *(const unsigned long long*)&Wb[k * COUTB + 2 * tx + 32 * p];
#pragma unroll
            for (int i = 0; i < 8; i++) {
                float av = Xb[(ty + i * 16) * 17 + k];
                unsigned long long ap = pack2(av, av);
#pragma unroll
                for (int p = 0; p < NP; p++) ffma2(acc[i][p], ap, bp[p]);
            }
        }
        __syncthreads();
    }
#pragma unroll
    for (int i = 0; i < 8; i++) {
        int r = ty + i * 16;
#pragma unroll
        for (int p = 0; p < NP; p++) {
            float lo, hi;
            unpack2(lo, hi, acc[i][p]);
            Hs[r * HS + 2 * tx + 32 * p]     = lo;
            Hs[r * HS + 2 * tx + 32 * p + 1] = hi;
        }
    }
    __syncthreads();

    // ---- aggregation: warp per dst, lanes = channels ----
    {
        const int warp = tid >> 5, lane = tid & 31;
#pragma unroll 1
        for (int dd = 0; dd < 16; dd++) {
            const int d = warp * 16 + dd;
            const int n = gbase + d;
            int cnt = (int)g_rowstart[n + 1] - (int)g_rowstart[n];
            if (cnt > ECAP) cnt = ECAP;
            const float dvd = g_dinv[n];
            const float sl2 = __fmul_rn(dvd, dvd);
            const int2* csp = g_cs + (size_t)n * ECAP;
            float acc0 = 0.f, acc1 = 0.f;
            int i = 0;
#pragma unroll 1
            for (; i + 4 <= cnt; i += 4) {
                int2 r0 = __ldg(csp + i);
                int2 r1 = __ldg(csp + i + 1);
                int2 r2 = __ldg(csp + i + 2);
                int2 r3 = __ldg(csp + i + 3);
                float c0 = __int_as_float(r0.x), c1v = __int_as_float(r1.x);
                float c2 = __int_as_float(r2.x), c3v = __int_as_float(r3.x);
                acc0 = __fadd_rn(acc0, __fmul_rn(Hs[r0.y * HS + lane], c0));
                if (COUTB == 64)
                    acc1 = __fadd_rn(acc1, __fmul_rn(Hs[r0.y * HS + 32 + lane], c0));
                acc0 = __fadd_rn(acc0, __fmul_rn(Hs[r1.y * HS + lane], c1v));
                if (COUTB == 64)
                    acc1 = __fadd_rn(acc1, __fmul_rn(Hs[r1.y * HS + 32 + lane], c1v));
                acc0 = __fadd_rn(acc0, __fmul_rn(Hs[r2.y * HS + lane], c2));
                if (COUTB == 64)
                    acc1 = __fadd_rn(acc1, __fmul_rn(Hs[r2.y * HS + 32 + lane], c2));
                acc0 = __fadd_rn(acc0, __fmul_rn(Hs[r3.y * HS + lane], c3v));
                if (COUTB == 64)
                    acc1 = __fadd_rn(acc1, __fmul_rn(Hs[r3.y * HS + 32 + lane], c3v));
            }
#pragma unroll 1
            for (; i < cnt; i++) {
                int2 r = __ldg(csp + i);
                float cf = __int_as_float(r.x);
                acc0 = __fadd_rn(acc0, __fmul_rn(Hs[r.y * HS + lane], cf));
                if (COUTB == 64)
                    acc1 = __fadd_rn(acc1, __fmul_rn(Hs[r.y * HS + 32 + lane], cf));
            }
            {
                float v = __fadd_rn(acc0, __fmul_rn(Hs[d * HS + lane], sl2));
                v = __fadd_rn(v, __ldg(&b[cb + lane]));
                g_hcat[(size_t)n * 256 + outoff + cb + lane] = tanh_xla(v);
            }
            if (COUTB == 64) {
                float v = __fadd_rn(acc1, __fmul_rn(Hs[d * HS + 32 + lane], sl2));
                v = __fadd_rn(v, __ldg(&b[cb + 32 + lane]));
                g_hcat[(size_t)n * 256 + outoff + cb + 32 + lane] = tanh_xla(v);
            }
        }
    }
}

__global__ __launch_bounds__(256) void k_gcn1(const float* __restrict__ x,
        const float* __restrict__ W, const float* __restrict__ b)
{ gcn_body<128, 128, 64>(x, 128, 0, W, b, 0); }
__global__ __launch_bounds__(256) void k_gcn2(const float* __restrict__ W,
        const float* __restrict__ b)
{ gcn_body<128, 64, 64>(g_hcat, 256, 0, W, b, 128); }
__global__ __launch_bounds__(256) void k_gcn3(const float* __restrict__ W,
        const float* __restrict__ b)
{ gcn_body<64, 32, 32>(g_hcat, 256, 128, W, b, 192); }
__global__ __launch_bounds__(256) void k_gcn4(const float* __restrict__ W,
        const float* __restrict__ b)
{ gcn_body<32, 32, 32>(g_hcat, 256, 192, W, b, 224); }

// ---------------- fused head (static smem ~43KB), PURE FP32 --------------------
#define TLS 257   // tile row stride: (tg*257+j)%32 = (tg+j)%32 -> conflict-free
__global__ __launch_bounds__(256) void k_head(
    const float* __restrict__ W5, const float* __restrict__ b5,
    const float* __restrict__ W6, const float* __restrict__ b6,
    const float* __restrict__ Wf1, const float* __restrict__ bf1,
    const float* __restrict__ Wf2, const float* __restrict__ bf2,
    float* __restrict__ out)
{
    __shared__ float W5s[4096];
    __shared__ float tile[16 * TLS];
    __shared__ float vals[128];
    __shared__ int   order[64];
    __shared__ float z[16 * 64];
    __shared__ float zp[16 * 32];
    __shared__ float y[896];
    __shared__ float f1[128];
    __shared__ float logits[10];
    __shared__ float red[2];

    const int g = blockIdx.x, tid = threadIdx.x;
    const float* hrow = g_hcat + (size_t)g * 128 * 256;

    if (tid < 128) vals[tid] = hrow[tid * 256 + 255];
    for (int i = tid; i < 4096; i += 256) W5s[i] = W5[i];
    __syncthreads();

    // stable descending rank (matches stable jnp.argsort(-v): ties -> lower idx)
    if (tid < 128) {
        float v = vals[tid];
        int rank = 0;
        for (int j = 0; j < 128; j++) {
            float vj = vals[j];
            rank += (vj > v) || (vj == v && j < tid);
        }
        if (rank < 64) order[rank] = tid;
    }
    __syncthreads();

    // Conv1d(1,16,256,256): tile 16 pooled rows into smem, then conflict-free LDS
    {
        const int c = tid >> 4, tg = tid & 15;
        const float bc = b5[c];
#pragma unroll 1
        for (int tt = 0; tt < 4; tt++) {
            for (int idx = tid; idx < 16 * 256; idx += 256) {
                int r = idx >> 8, j = idx & 255;
                tile[r * TLS + j] = hrow[(size_t)order[tt * 16 + r] * 256 + j];
            }
            __syncthreads();
            float a0 = 0.f;
#pragma unroll 4
            for (int j = 0; j < 256; j++)
                a0 = fmaf(tile[tg * TLS + j], W5s[c * 256 + j], a0);
            z[c * 64 + tt * 16 + tg] = fmaxf(__fadd_rn(a0, bc), 0.f);
            __syncthreads();
        }
    }

    // MaxPool1d(2,2)
    for (int idx = tid; idx < 512; idx += 256) {
        int c = idx >> 5, u = idx & 31;
        zp[c * 32 + u] = fmaxf(z[c * 64 + 2 * u], z[c * 64 + 2 * u + 1]);
    }
    __syncthreads();

    // Conv1d(16,32,5) VALID + relu (W6 via __ldg; 10KB, L1-resident)
    for (int idx = tid; idx < 896; idx += 256) {
        int o = idx / 28, t = idx - o * 28;
        float a0 = 0.f;
#pragma unroll
        for (int i = 0; i < 16; i++)
#pragma unroll
            for (int k = 0; k < 5; k++)
                a0 = fmaf(zp[i * 32 + t + k], __ldg(&W6[(o * 16 + i) * 5 + k]), a0);
        y[idx] = fmaxf(__fadd_rn(a0, b6[o]), 0.f);
    }
    __syncthreads();

    // FC1 896->128 relu
    if (tid < 128) {
        float a0 = 0.f;
#pragma unroll 8
        for (int i = 0; i < 896; i++)
            a0 = fmaf(y[i], __ldg(&Wf1[(size_t)i * 128 + tid]), a0);
        f1[tid] = fmaxf(__fadd_rn(a0, bf1[tid]), 0.f);
    }
    __syncthreads();

    // FC2 128->10
    if (tid < 10) {
        float a0 = 0.f;
#pragma unroll 8
        for (int j = 0; j < 128; j++)
            a0 = fmaf(f1[j], __ldg(&Wf2[j * 10 + tid]), a0);
        logits[tid] = __fadd_rn(a0, bf2[tid]);
    }
    __syncthreads();
    if (tid == 0) {
        float m = logits[0];
        for (int k = 1; k < 10; k++) m = fmaxf(m, logits[k]);
        float s = 0.f;
        for (int k = 0; k < 10; k++) s += expf(logits[k] - m);
        red[0] = m;
        red[1] = logf(s);
    }
    __syncthreads();
    if (tid < 10) out[g * 10 + tid] = logits[tid] - red[0] - red[1];
}

// ---------------- launch (no dynamic smem, no attributes) -----------------------
extern "C" void kernel_launch(void* const* d_in, const int* in_sizes, int n_in,
                              void* d_out, int out_size)
{
    const float* x   = (const float*)d_in[0];
    const float* W1  = (const float*)d_in[1];
    const float* b1  = (const float*)d_in[2];
    const float* W2  = (const float*)d_in[3];
    const float* b2  = (const float*)d_in[4];
    const float* W3  = (const float*)d_in[5];
    const float* b3  = (const float*)d_in[6];
    const float* W4  = (const float*)d_in[7];
    const float* b4  = (const float*)d_in[8];
    const float* W5  = (const float*)d_in[9];
    const float* b5  = (const float*)d_in[10];
    const float* W6  = (const float*)d_in[11];
    const float* b6  = (const float*)d_in[12];
    const float* Wf1 = (const float*)d_in[13];
    const float* bf1 = (const float*)d_in[14];
    const float* Wf2 = (const float*)d_in[15];
    const float* bf2 = (const float*)d_in[16];
    const int*   ei  = (const int*)d_in[17];
    const int* src = ei;
    const int* dst = ei + NEDGES;
    float* out = (float*)d_out;

    // degree + CSR + deterministic per-dst edge lists
    k_zero_cnt<<<NNODES / 256, 256>>>();
    k_count<<<NEDGES / 256, 256>>>(dst);
    k_scan1<<<256, 256>>>();
    k_scan2<<<1, 256>>>();
    k_scan3<<<NNODES / 256, 256>>>();
    k_scatter<<<NEDGES / 256, 256>>>(dst);
    k_edges<<<NNODES / 256, 256>>>(src);

    // GCN layers -> concat buffer columns 0,128,192,224
    k_gcn1<<<dim3(NG, 2), 256>>>(x, W1, b1);
    k_gcn2<<<dim3(NG, 1), 256>>>(W2, b2);
    k_gcn3<<<dim3(NG, 1), 256>>>(W3, b3);
    k_gcn4<<<dim3(NG, 1), 256>>>(W4, b4);

    // sort-pool + convs + MLP + log_softmax
    k_head<<<NG, 256>>>(W5, b5, W6, b6, Wf1, bf1, Wf2, bf2, out);
}

// round 15
// speedup vs baseline: 1.7941x; 1.0241x over previous
#include <cuda_runtime.h>
#include <math.h>

#define NNODES 65536
#define NEDGES 1048576
#define NG 512
#define ECAP 48   // per-dst capacity: Binomial(2048,1/128); P(any node >48) ~ 1e-10

// ---------------- device scratch (allocation-free: __device__ globals) -------
__device__ __align__(16) float    g_dinv[NNODES];
__device__ __align__(16) unsigned g_cnt[NNODES];
__device__ __align__(16) unsigned g_rowstart[NNODES + 1];
__device__ __align__(16) unsigned g_fill[NNODES];
__device__ __align__(16) unsigned g_bsum[256];
__device__ __align__(16) int      g_eid[NEDGES];
__device__ __align__(16) int2     g_cs[(size_t)NNODES * ECAP];   // {coef bits, slocal}
__device__ __align__(16) float    g_hcat[(size_t)NNODES * 256];

// ---------------- packed f32x2 helpers (bitwise = two scalar fp32 FMAs) -------
__device__ __forceinline__ void unpack2(float& lo, float& hi, unsigned long long v) {
    asm("mov.b64 {%0,%1}, %2;" : "=f"(lo), "=f"(hi) : "l"(v));
}
__device__ __forceinline__ void ffma2(unsigned long long& d,
                                      unsigned long long a, unsigned long long b) {
    asm("fma.rn.f32x2 %0, %1, %2, %0;" : "+l"(d) : "l"(a), "l"(b));
}

// ---------------- XLA f32 tanh: rational approx, NO FMA (XLA emits mul+add) ---
__device__ __forceinline__ float tanh_xla(float x) {
    const float kMax = 7.90531110763549805f;
    float ax = fabsf(x);
    float xc = fminf(fmaxf(x, -kMax), kMax);
    float x2 = __fmul_rn(xc, xc);
    float p = -2.76076847742355e-16f;
    p = __fadd_rn(__fmul_rn(p, x2),  2.00018790482477e-13f);
    p = __fadd_rn(__fmul_rn(p, x2), -8.60467152213735e-11f);
    p = __fadd_rn(__fmul_rn(p, x2),  5.12229709037114e-08f);
    p = __fadd_rn(__fmul_rn(p, x2),  1.48572235717979e-05f);
    p = __fadd_rn(__fmul_rn(p, x2),  6.37261928875436e-04f);
    p = __fadd_rn(__fmul_rn(p, x2),  4.89352455891786e-03f);
    p = __fmul_rn(xc, p);
    float q = 1.19825839466702e-06f;
    q = __fadd_rn(__fmul_rn(q, x2),  1.18534705686654e-04f);
    q = __fadd_rn(__fmul_rn(q, x2),  2.26843463243900e-03f);
    q = __fadd_rn(__fmul_rn(q, x2),  4.89352518554385e-03f);
    float r = __fdiv_rn(p, q);
    return (ax < 0.0004f) ? x : r;
}

// ---------------- degree counting / CSR build ---------------------------------
__global__ void k_zero_cnt() {
    int i = blockIdx.x * blockDim.x + threadIdx.x;
    if (i < NNODES) g_cnt[i] = 0u;
}
__global__ void k_count(const int* __restrict__ dst) {
    int e = blockIdx.x * blockDim.x + threadIdx.x;
    if (e < NEDGES) atomicAdd(&g_cnt[dst[e]], 1u);
}
// scan stage 1 + dinv fused
__global__ void k_scan1() {
    __shared__ unsigned s[256];
    int t = threadIdx.x;
    int i = blockIdx.x * 256 + t;
    unsigned v = g_cnt[i];
    g_dinv[i] = rsqrtf((float)(v + 1u));
    s[t] = v;
    __syncthreads();
    for (int off = 1; off < 256; off <<= 1) {
        unsigned u = (t >= off) ? s[t - off] : 0u;
        __syncthreads();
        s[t] += u;
        __syncthreads();
    }
    g_rowstart[i] = s[t] - v;
    if (t == 255) g_bsum[blockIdx.x] = s[255];
}
__global__ void k_scan2() {
    __shared__ unsigned s[256];
    int t = threadIdx.x;
    unsigned v = g_bsum[t];
    s[t] = v;
    __syncthreads();
    for (int off = 1; off < 256; off <<= 1) {
        unsigned u = (t >= off) ? s[t - off] : 0u;
        __syncthreads();
        s[t] += u;
        __syncthreads();
    }
    g_bsum[t] = s[t] - v;
}
__global__ void k_scan3() {
    int i = blockIdx.x * blockDim.x + threadIdx.x;
    if (i < NNODES) {
        unsigned r = g_rowstart[i] + g_bsum[i >> 8];
        g_rowstart[i] = r;
        g_fill[i] = r;
    }
    if (i == 0) g_rowstart[NNODES] = NEDGES;
}
__global__ void k_scatter(const int* __restrict__ dst) {
    int e = blockIdx.x * blockDim.x + threadIdx.x;
    if (e < NEDGES) {
        unsigned p = atomicAdd(&g_fill[dst[e]], 1u);
        g_eid[p] = e;
    }
}
// per-dst edge lists: ascending edge id (deterministic), packed {coef, slocal}
// sort buffer in padded smem (stride 49 -> conflict-free, no local-mem spill)
__global__ __launch_bounds__(128) void k_edges(const int* __restrict__ srcArr) {
    __shared__ int sids[128 * 49];
    int tid = threadIdx.x;
    int n = blockIdx.x * 128 + tid;
    int* ids = sids + tid * 49;
    int base = (int)g_rowstart[n];
    int cnt  = (int)g_rowstart[n + 1] - base;
    if (cnt > ECAP) cnt = ECAP;
    for (int i = 0; i < cnt; i++) ids[i] = g_eid[base + i];
    for (int i = 1; i < cnt; i++) {
        int key = ids[i], j = i - 1;
        while (j >= 0 && ids[j] > key) { ids[j + 1] = ids[j]; j--; }
        ids[j + 1] = key;
    }
    float dvd = g_dinv[n];
    for (int i = 0; i < cnt; i++) {
        int s = srcArr[ids[i]];
        int2 rec;
        rec.x = __float_as_int(__fmul_rn(g_dinv[s], dvd));
        rec.y = s & 127;
        g_cs[(size_t)n * ECAP + i] = rec;
    }
}

// ---------------- GCN layer body: one CTA per (graph, channel-block) -----------
// PURE FP32, bitwise-stable. GEMM: fma.rn.f32x2 with pre-duplicated X tile
// (LDS.64 A operand, zero MOVs). Aggregation: warp-per-dst, 2 dsts interleaved
// (each dst's edge chain still ascending edge id -> bitwise identical).
template <int CIN, int COUT, int COUTB>
__device__ __forceinline__ void gcn_body(
    const float* __restrict__ xin, int xstride, int xoff,
    const float* __restrict__ W, const float* __restrict__ b, int outoff)
{
    constexpr int HS = COUTB + 1;
    constexpr int NP = COUTB / 32;     // u64 col-pairs per thread
    constexpr int KB = 8;
    __shared__ float Hs[128 * HS];
    __shared__ __align__(16) float2 XbD[128 * (KB + 1)];   // (v,v) duplicated
    __shared__ __align__(16) float  Wb[KB * COUTB];

    const int tid = threadIdx.x;
    const int ty  = tid >> 4;
    const int tx  = tid & 15;
    const int gbase = blockIdx.x << 7;
    const int cb    = blockIdx.y * COUTB;

    // ---- GEMM: H(:, cb:cb+COUTB) = X @ W(:, cb:cb+COUTB) ----
    unsigned long long acc[8][NP];
#pragma unroll
    for (int i = 0; i < 8; i++)
#pragma unroll
        for (int p = 0; p < NP; p++) acc[i][p] = 0ull;

    for (int kb = 0; kb < CIN; kb += KB) {
        for (int idx = tid; idx < 128 * KB; idx += 256) {
            int r = idx >> 3, k = idx & 7;
            float v = xin[(size_t)(gbase + r) * xstride + xoff + kb + k];
            XbD[r * (KB + 1) + k] = make_float2(v, v);
        }
        for (int idx = tid; idx < KB * COUTB; idx += 256) {
            int k = idx / COUTB, c = idx - k * COUTB;
            Wb[k * COUTB + c] = W[(size_t)(kb + k) * COUT + cb + c];
        }
        __syncthreads();
#pragma unroll
        for (int k = 0; k < KB; k++) {
            unsigned long long bp[NP];
#pragma unroll
            for (int p = 0; p < NP; p++)
                bp[p] = *(const unsigned long long*)&Wb[k * COUTB + 2 * tx + 32 * p];
#pragma unroll
            for (int i = 0; i < 8; i++) {
                unsigned long long ap =
                    *(const unsigned long long*)&XbD[(ty + i * 16) * (KB + 1) + k];
#pragma unroll
                for (int p = 0; p < NP; p++) ffma2(acc[i][p], ap, bp[p]);
            }
        }
        __syncthreads();
    }
#pragma unroll
    for (int i = 0; i < 8; i++) {
        int r = ty + i * 16;
#pragma unroll
        for (int p = 0; p < NP; p++) {
            float lo, hi;
            unpack2(lo, hi, acc[i][p]);
            Hs[r * HS + 2 * tx + 32 * p]     = lo;
            Hs[r * HS + 2 * tx + 32 * p + 1] = hi;
        }
    }
    __syncthreads();

    // ---- aggregation: warp per dst, lanes = channels, 2 dsts interleaved ----
    {
        const int warp = tid >> 5, lane = tid & 31;
#pragma unroll 1
        for (int dd = 0; dd < 16; dd += 2) {
            const int d0 = warp * 16 + dd,     n0 = gbase + d0;
            const int d1 = warp * 16 + dd + 1, n1 = gbase + d1;
            int cnt0 = (int)g_rowstart[n0 + 1] - (int)g_rowstart[n0];
            int cnt1 = (int)g_rowstart[n1 + 1] - (int)g_rowstart[n1];
            if (cnt0 > ECAP) cnt0 = ECAP;
            if (cnt1 > ECAP) cnt1 = ECAP;
            const int2* cs0 = g_cs + (size_t)n0 * ECAP;
            const int2* cs1 = g_cs + (size_t)n1 * ECAP;
            float a00 = 0.f, a01 = 0.f, a10 = 0.f, a11 = 0.f;
            const int common = cnt0 < cnt1 ? cnt0 : cnt1;
            int i = 0;
#pragma unroll 1
            for (; i + 2 <= common; i += 2) {
                int2 p0 = __ldg(cs0 + i), p1 = __ldg(cs0 + i + 1);
                int2 q0 = __ldg(cs1 + i), q1 = __ldg(cs1 + i + 1);
                float pc0 = __int_as_float(p0.x), pc1 = __int_as_float(p1.x);
                float qc0 = __int_as_float(q0.x), qc1 = __int_as_float(q1.x);
                a00 = __fadd_rn(a00, __fmul_rn(Hs[p0.y * HS + lane], pc0));
                if (COUTB == 64)
                    a01 = __fadd_rn(a01, __fmul_rn(Hs[p0.y * HS + 32 + lane], pc0));
                a00 = __fadd_rn(a00, __fmul_rn(Hs[p1.y * HS + lane], pc1));
                if (COUTB == 64)
                    a01 = __fadd_rn(a01, __fmul_rn(Hs[p1.y * HS + 32 + lane], pc1));
                a10 = __fadd_rn(a10, __fmul_rn(Hs[q0.y * HS + lane], qc0));
                if (COUTB == 64)
                    a11 = __fadd_rn(a11, __fmul_rn(Hs[q0.y * HS + 32 + lane], qc0));
                a10 = __fadd_rn(a10, __fmul_rn(Hs[q1.y * HS + lane], qc1));
                if (COUTB == 64)
                    a11 = __fadd_rn(a11, __fmul_rn(Hs[q1.y * HS + 32 + lane], qc1));
            }
#pragma unroll 1
            for (; i < common; i++) {
                int2 p = __ldg(cs0 + i), q = __ldg(cs1 + i);
                float pc = __int_as_float(p.x), qc = __int_as_float(q.x);
                a00 = __fadd_rn(a00, __fmul_rn(Hs[p.y * HS + lane], pc));
                if (COUTB == 64)
                    a01 = __fadd_rn(a01, __fmul_rn(Hs[p.y * HS + 32 + lane], pc));
                a10 = __fadd_rn(a10, __fmul_rn(Hs[q.y * HS + lane], qc));
                if (COUTB == 64)
                    a11 = __fadd_rn(a11, __fmul_rn(Hs[q.y * HS + 32 + lane], qc));
            }
#pragma unroll 1
            for (int j = i; j < cnt0; j++) {
                int2 p = __ldg(cs0 + j);
                float pc = __int_as_float(p.x);
                a00 = __fadd_rn(a00, __fmul_rn(Hs[p.y * HS + lane], pc));
                if (COUTB == 64)
                    a01 = __fadd_rn(a01, __fmul_rn(Hs[p.y * HS + 32 + lane], pc));
            }
#pragma unroll 1
            for (int j = i; j < cnt1; j++) {
                int2 q = __ldg(cs1 + j);
                float qc = __int_as_float(q.x);
                a10 = __fadd_rn(a10, __fmul_rn(Hs[q.y * HS + lane], qc));
                if (COUTB == 64)
                    a11 = __fadd_rn(a11, __fmul_rn(Hs[q.y * HS + 32 + lane], qc));
            }
            // epilogue dst0
            {
                float dvd = g_dinv[n0];
                float sl2 = __fmul_rn(dvd, dvd);
                float v = __fadd_rn(a00, __fmul_rn(Hs[d0 * HS + lane], sl2));
                v = __fadd_rn(v, __ldg(&b[cb + lane]));
                g_hcat[(size_t)n0 * 256 + outoff + cb + lane] = tanh_xla(v);
                if (COUTB == 64) {
                    float w = __fadd_rn(a01, __fmul_rn(Hs[d0 * HS + 32 + lane], sl2));
                    w = __fadd_rn(w, __ldg(&b[cb + 32 + lane]));
                    g_hcat[(size_t)n0 * 256 + outoff + cb + 32 + lane] = tanh_xla(w);
                }
            }
            // epilogue dst1
            {
                float dvd = g_dinv[n1];
                float sl2 = __fmul_rn(dvd, dvd);
                float v = __fadd_rn(a10, __fmul_rn(Hs[d1 * HS + lane], sl2));
                v = __fadd_rn(v, __ldg(&b[cb + lane]));
                g_hcat[(size_t)n1 * 256 + outoff + cb + lane] = tanh_xla(v);
                if (COUTB == 64) {
                    float w = __fadd_rn(a11, __fmul_rn(Hs[d1 * HS + 32 + lane], sl2));
                    w = __fadd_rn(w, __ldg(&b[cb + 32 + lane]));
                    g_hcat[(size_t)n1 * 256 + outoff + cb + 32 + lane] = tanh_xla(w);
                }
            }
        }
    }
}

__global__ __launch_bounds__(256) void k_gcn1(const float* __restrict__ x,
        const float* __restrict__ W, const float* __restrict__ b)
{ gcn_body<128, 128, 64>(x, 128, 0, W, b, 0); }
__global__ __launch_bounds__(256) void k_gcn2(const float* __restrict__ W,
        const float* __restrict__ b)
{ gcn_body<128, 64, 64>(g_hcat, 256, 0, W, b, 128); }
__global__ __launch_bounds__(256) void k_gcn3(const float* __restrict__ W,
        const float* __restrict__ b)
{ gcn_body<64, 32, 32>(g_hcat, 256, 128, W, b, 192); }
__global__ __launch_bounds__(256) void k_gcn4(const float* __restrict__ W,
        const float* __restrict__ b)
{ gcn_body<32, 32, 32>(g_hcat, 256, 192, W, b, 224); }

// ---------------- fused head (static smem ~43KB), PURE FP32 --------------------
#define TLS 257   // tile row stride: conflict-free
__global__ __launch_bounds__(256) void k_head(
    const float* __restrict__ W5, const float* __restrict__ b5,
    const float* __restrict__ W6, const float* __restrict__ b6,
    const float* __restrict__ Wf1, const float* __restrict__ bf1,
    const float* __restrict__ Wf2, const float* __restrict__ bf2,
    float* __restrict__ out)
{
    __shared__ float W5s[4096];
    __shared__ float tile[16 * TLS];
    __shared__ float vals[128];
    __shared__ int   order[64];
    __shared__ float z[16 * 64];
    __shared__ float zp[16 * 32];
    __shared__ float y[896];
    __shared__ float f1[128];
    __shared__ float logits[10];
    __shared__ float red[2];

    const int g = blockIdx.x, tid = threadIdx.x;
    const float* hrow = g_hcat + (size_t)g * 128 * 256;

    if (tid < 128) vals[tid] = hrow[tid * 256 + 255];
    for (int i = tid; i < 4096; i += 256) W5s[i] = W5[i];
    __syncthreads();

    // stable descending rank (matches stable jnp.argsort(-v): ties -> lower idx)
    if (tid < 128) {
        float v = vals[tid];
        int rank = 0;
        for (int j = 0; j < 128; j++) {
            float vj = vals[j];
            rank += (vj > v) || (vj == v && j < tid);
        }
        if (rank < 64) order[rank] = tid;
    }
    __syncthreads();

    // Conv1d(1,16,256,256): tile 16 pooled rows into smem, conflict-free LDS
    {
        const int c = tid >> 4, tg = tid & 15;
        const float bc = b5[c];
#pragma unroll 1
        for (int tt = 0; tt < 4; tt++) {
            for (int idx = tid; idx < 16 * 256; idx += 256) {
                int r = idx >> 8, j = idx & 255;
                tile[r * TLS + j] = hrow[(size_t)order[tt * 16 + r] * 256 + j];
            }
            __syncthreads();
            float a0 = 0.f;
#pragma unroll 4
            for (int j = 0; j < 256; j++)
                a0 = fmaf(tile[tg * TLS + j], W5s[c * 256 + j], a0);
            z[c * 64 + tt * 16 + tg] = fmaxf(__fadd_rn(a0, bc), 0.f);
            __syncthreads();
        }
    }

    // MaxPool1d(2,2)
    for (int idx = tid; idx < 512; idx += 256) {
        int c = idx >> 5, u = idx & 31;
        zp[c * 32 + u] = fmaxf(z[c * 64 + 2 * u], z[c * 64 + 2 * u + 1]);
    }
    __syncthreads();

    // Conv1d(16,32,5) VALID + relu (W6 via __ldg)
    for (int idx = tid; idx < 896; idx += 256) {
        int o = idx / 28, t = idx - o * 28;
        float a0 = 0.f;
#pragma unroll
        for (int i = 0; i < 16; i++)
#pragma unroll
            for (int k = 0; k < 5; k++)
                a0 = fmaf(zp[i * 32 + t + k], __ldg(&W6[(o * 16 + i) * 5 + k]), a0);
        y[idx] = fmaxf(__fadd_rn(a0, b6[o]), 0.f);
    }
    __syncthreads();

    // FC1 896->128 relu
    if (tid < 128) {
        float a0 = 0.f;
#pragma unroll 8
        for (int i = 0; i < 896; i++)
            a0 = fmaf(y[i], __ldg(&Wf1[(size_t)i * 128 + tid]), a0);
        f1[tid] = fmaxf(__fadd_rn(a0, bf1[tid]), 0.f);
    }
    __syncthreads();

    // FC2 128->10
    if (tid < 10) {
        float a0 = 0.f;
#pragma unroll 8
        for (int j = 0; j < 128; j++)
            a0 = fmaf(f1[j], __ldg(&Wf2[j * 10 + tid]), a0);
        logits[tid] = __fadd_rn(a0, bf2[tid]);
    }
    __syncthreads();
    if (tid == 0) {
        float m = logits[0];
        for (int k = 1; k < 10; k++) m = fmaxf(m, logits[k]);
        float s = 0.f;
        for (int k = 0; k < 10; k++) s += expf(logits[k] - m);
        red[0] = m;
        red[1] = logf(s);
    }
    __syncthreads();
    if (tid < 10) out[g * 10 + tid] = logits[tid] - red[0] - red[1];
}

// ---------------- launch (no dynamic smem, no attributes) -----------------------
extern "C" void kernel_launch(void* const* d_in, const int* in_sizes, int n_in,
                              void* d_out, int out_size)
{
    const float* x   = (const float*)d_in[0];
    const float* W1  = (const float*)d_in[1];
    const float* b1  = (const float*)d_in[2];
    const float* W2  = (const float*)d_in[3];
    const float* b2  = (const float*)d_in[4];
    const float* W3  = (const float*)d_in[5];
    const float* b3  = (const float*)d_in[6];
    const float* W4  = (const float*)d_in[7];
    const float* b4  = (const float*)d_in[8];
    const float* W5  = (const float*)d_in[9];
    const float* b5  = (const float*)d_in[10];
    const float* W6  = (const float*)d_in[11];
    const float* b6  = (const float*)d_in[12];
    const float* Wf1 = (const float*)d_in[13];
    const float* bf1 = (const float*)d_in[14];
    const float* Wf2 = (const float*)d_in[15];
    const float* bf2 = (const float*)d_in[16];
    const int*   ei  = (const int*)d_in[17];
    const int* src = ei;
    const int* dst = ei + NEDGES;
    float* out = (float*)d_out;

    // degree + CSR + deterministic per-dst edge lists
    k_zero_cnt<<<NNODES / 256, 256>>>();
    k_count<<<NEDGES / 256, 256>>>(dst);
    k_scan1<<<256, 256>>>();
    k_scan2<<<1, 256>>>();
    k_scan3<<<NNODES / 256, 256>>>();
    k_scatter<<<NEDGES / 256, 256>>>(dst);
    k_edges<<<NNODES / 128, 128>>>(src);

    // GCN layers -> concat buffer columns 0,128,192,224
    k_gcn1<<<dim3(NG, 2), 256>>>(x, W1, b1);
    k_gcn2<<<dim3(NG, 1), 256>>>(W2, b2);
    k_gcn3<<<dim3(NG, 1), 256>>>(W3, b3);
    k_gcn4<<<dim3(NG, 1), 256>>>(W4, b4);

    // sort-pool + convs + MLP + log_softmax
    k_head<<<NG, 256>>>(W5, b5, W6, b6, Wf1, bf1, Wf2, bf2, out);
}

// round 16
// speedup vs baseline: 1.8795x; 1.0476x over previous
#include <cuda_runtime.h>
#include <math.h>

#define NNODES 65536
#define NEDGES 1048576
#define NG 512
#define ECAP 48   // per-dst capacity: Binomial(2048,1/128); P(any node >48) ~ 1e-10

// ---------------- device scratch (allocation-free: __device__ globals) -------
__device__ __align__(16) float    g_dinv[NNODES];
__device__ __align__(16) unsigned g_cnt[NNODES];
__device__ __align__(16) int      g_eid[(size_t)NNODES * ECAP];
__device__ __align__(16) int2     g_cs[(size_t)NNODES * ECAP];   // {coef bits, slocal}
__device__ __align__(16) float    g_hcat[(size_t)NNODES * 256];

// ---------------- packed f32x2 helpers (bitwise = two scalar fp32 FMAs) -------
__device__ __forceinline__ void unpack2(float& lo, float& hi, unsigned long long v) {
    asm("mov.b64 {%0,%1}, %2;" : "=f"(lo), "=f"(hi) : "l"(v));
}
__device__ __forceinline__ void ffma2(unsigned long long& d,
                                      unsigned long long a, unsigned long long b) {
    asm("fma.rn.f32x2 %0, %1, %2, %0;" : "+l"(d) : "l"(a), "l"(b));
}

// ---------------- XLA f32 tanh: rational approx, NO FMA (XLA emits mul+add) ---
__device__ __forceinline__ float tanh_xla(float x) {
    const float kMax = 7.90531110763549805f;
    float ax = fabsf(x);
    float xc = fminf(fmaxf(x, -kMax), kMax);
    float x2 = __fmul_rn(xc, xc);
    float p = -2.76076847742355e-16f;
    p = __fadd_rn(__fmul_rn(p, x2),  2.00018790482477e-13f);
    p = __fadd_rn(__fmul_rn(p, x2), -8.60467152213735e-11f);
    p = __fadd_rn(__fmul_rn(p, x2),  5.12229709037114e-08f);
    p = __fadd_rn(__fmul_rn(p, x2),  1.48572235717979e-05f);
    p = __fadd_rn(__fmul_rn(p, x2),  6.37261928875436e-04f);
    p = __fadd_rn(__fmul_rn(p, x2),  4.89352455891786e-03f);
    p = __fmul_rn(xc, p);
    float q = 1.19825839466702e-06f;
    q = __fadd_rn(__fmul_rn(q, x2),  1.18534705686654e-04f);
    q = __fadd_rn(__fmul_rn(q, x2),  2.26843463243900e-03f);
    q = __fadd_rn(__fmul_rn(q, x2),  4.89352518554385e-03f);
    float r = __fdiv_rn(p, q);
    return (ax < 0.0004f) ? x : r;
}

// ---------------- count + scatter fused (fixed per-node slots) -----------------
// Arrival order into slots is racy, but k_edges sorts ascending edge id ->
// canonical deterministic lists (same set: drop risk only if cnt>48, P~1e-10).
__global__ void k_count_scatter(const int* __restrict__ src,
                                const int* __restrict__ dst) {
    int e = blockIdx.x * blockDim.x + threadIdx.x;
    if (e < NEDGES) {
        int n = dst[e];
        unsigned p = atomicAdd(&g_cnt[n], 1u);
        if (p < ECAP) g_eid[(size_t)n * ECAP + p] = e;
    }
}
// per-dst lists: sort ascending edge id, compute coef (bitwise same rsqrtf/mul
// as before), write packed {coef, slocal}; also writes g_dinv[n].
__global__ __launch_bounds__(128) void k_edges(const int* __restrict__ srcArr) {
    __shared__ int sids[128 * 49];
    int tid = threadIdx.x;
    int n = blockIdx.x * 128 + tid;
    int* ids = sids + tid * 49;
    int cnt = (int)g_cnt[n];
    if (cnt > ECAP) cnt = ECAP;
    for (int i = 0; i < cnt; i++) ids[i] = g_eid[(size_t)n * ECAP + i];
    for (int i = 1; i < cnt; i++) {
        int key = ids[i], j = i - 1;
        while (j >= 0 && ids[j] > key) { ids[j + 1] = ids[j]; j--; }
        ids[j + 1] = key;
    }
    float dvd = rsqrtf((float)(g_cnt[n] + 1u));
    g_dinv[n] = dvd;
    for (int i = 0; i < cnt; i++) {
        int s = srcArr[ids[i]];
        int2 rec;
        rec.x = __float_as_int(__fmul_rn(rsqrtf((float)(g_cnt[s] + 1u)), dvd));
        rec.y = s & 127;
        g_cs[(size_t)n * ECAP + i] = rec;
    }
}

// ---------------- GCN phase (device func, smem unioned) ------------------------
// PURE FP32, bitwise-stable vs R12-R15: FFMA2 GEMM with pre-duplicated X tile,
// warp-per-dst aggregation with 2 dsts interleaved (per-dst ascending order).
template <int CIN, int COUT, int COUTB>
__device__ __forceinline__ void gcn_phase(
    unsigned char* smraw,
    const float* __restrict__ xin, int xstride, int xoff,
    const float* __restrict__ W, const float* __restrict__ b, int outoff)
{
    constexpr int HS = COUTB + 1;
    constexpr int NP = COUTB / 32;
    constexpr int KB = 8;
    float*  Hs  = (float*)smraw;                  // up to 128*65 floats (33280B)
    float2* XbD = (float2*)(smraw + 33280);       // 128*(KB+1) float2 (9216B)
    float*  Wb  = (float*)(smraw + 42496);        // KB*COUTB floats (<=2048B)

    const int tid = threadIdx.x;
    const int ty  = tid >> 4;
    const int tx  = tid & 15;
    const int gbase = blockIdx.x << 7;

    for (int cb = 0; cb < COUT; cb += COUTB) {
        unsigned long long acc[8][NP];
#pragma unroll
        for (int i = 0; i < 8; i++)
#pragma unroll
            for (int p = 0; p < NP; p++) acc[i][p] = 0ull;

        for (int kb = 0; kb < CIN; kb += KB) {
            for (int idx = tid; idx < 128 * KB; idx += 256) {
                int r = idx >> 3, k = idx & 7;
                float v = xin[(size_t)(gbase + r) * xstride + xoff + kb + k];
                XbD[r * (KB + 1) + k] = make_float2(v, v);
            }
            for (int idx = tid; idx < KB * COUTB; idx += 256) {
                int k = idx / COUTB, c = idx - k * COUTB;
                Wb[k * COUTB + c] = W[(size_t)(kb + k) * COUT + cb + c];
            }
            __syncthreads();
#pragma unroll
            for (int k = 0; k < KB; k++) {
                unsigned long long bp[NP];
#pragma unroll
                for (int p = 0; p < NP; p++)
                    bp[p] = *(const unsigned long long*)&Wb[k * COUTB + 2 * tx + 32 * p];
#pragma unroll
                for (int i = 0; i < 8; i++) {
                    unsigned long long ap =
                        *(const unsigned long long*)&XbD[(ty + i * 16) * (KB + 1) + k];
#pragma unroll
                    for (int p = 0; p < NP; p++) ffma2(acc[i][p], ap, bp[p]);
                }
            }
            __syncthreads();
        }
#pragma unroll
        for (int i = 0; i < 8; i++) {
            int r = ty + i * 16;
#pragma unroll
            for (int p = 0; p < NP; p++) {
                float lo, hi;
                unpack2(lo, hi, acc[i][p]);
                Hs[r * HS + 2 * tx + 32 * p]     = lo;
                Hs[r * HS + 2 * tx + 32 * p + 1] = hi;
            }
        }
        __syncthreads();

        // ---- aggregation: warp per dst, lanes = channels, 2 dsts interleaved
        {
            const int warp = tid >> 5, lane = tid & 31;
#pragma unroll 1
            for (int dd = 0; dd < 16; dd += 2) {
                const int d0 = warp * 16 + dd,     n0 = gbase + d0;
                const int d1 = warp * 16 + dd + 1, n1 = gbase + d1;
                int cnt0 = (int)g_cnt[n0]; if (cnt0 > ECAP) cnt0 = ECAP;
                int cnt1 = (int)g_cnt[n1]; if (cnt1 > ECAP) cnt1 = ECAP;
                const int2* cs0 = g_cs + (size_t)n0 * ECAP;
                const int2* cs1 = g_cs + (size_t)n1 * ECAP;
                float a00 = 0.f, a01 = 0.f, a10 = 0.f, a11 = 0.f;
                const int common = cnt0 < cnt1 ? cnt0 : cnt1;
                int i = 0;
#pragma unroll 1
                for (; i + 2 <= common; i += 2) {
                    int2 p0 = __ldg(cs0 + i), p1 = __ldg(cs0 + i + 1);
                    int2 q0 = __ldg(cs1 + i), q1 = __ldg(cs1 + i + 1);
                    float pc0 = __int_as_float(p0.x), pc1 = __int_as_float(p1.x);
                    float qc0 = __int_as_float(q0.x), qc1 = __int_as_float(q1.x);
                    a00 = __fadd_rn(a00, __fmul_rn(Hs[p0.y * HS + lane], pc0));
                    if (COUTB == 64)
                        a01 = __fadd_rn(a01, __fmul_rn(Hs[p0.y * HS + 32 + lane], pc0));
                    a00 = __fadd_rn(a00, __fmul_rn(Hs[p1.y * HS + lane], pc1));
                    if (COUTB == 64)
                        a01 = __fadd_rn(a01, __fmul_rn(Hs[p1.y * HS + 32 + lane], pc1));
                    a10 = __fadd_rn(a10, __fmul_rn(Hs[q0.y * HS + lane], qc0));
                    if (COUTB == 64)
                        a11 = __fadd_rn(a11, __fmul_rn(Hs[q0.y * HS + 32 + lane], qc0));
                    a10 = __fadd_rn(a10, __fmul_rn(Hs[q1.y * HS + lane], qc1));
                    if (COUTB == 64)
                        a11 = __fadd_rn(a11, __fmul_rn(Hs[q1.y * HS + 32 + lane], qc1));
                }
#pragma unroll 1
                for (; i < common; i++) {
                    int2 p = __ldg(cs0 + i), q = __ldg(cs1 + i);
                    float pc = __int_as_float(p.x), qc = __int_as_float(q.x);
                    a00 = __fadd_rn(a00, __fmul_rn(Hs[p.y * HS + lane], pc));
                    if (COUTB == 64)
                        a01 = __fadd_rn(a01, __fmul_rn(Hs[p.y * HS + 32 + lane], pc));
                    a10 = __fadd_rn(a10, __fmul_rn(Hs[q.y * HS + lane], qc));
                    if (COUTB == 64)
                        a11 = __fadd_rn(a11, __fmul_rn(Hs[q.y * HS + 32 + lane], qc));
                }
#pragma unroll 1
                for (int j = i; j < cnt0; j++) {
                    int2 p = __ldg(cs0 + j);
                    float pc = __int_as_float(p.x);
                    a00 = __fadd_rn(a00, __fmul_rn(Hs[p.y * HS + lane], pc));
                    if (COUTB == 64)
                        a01 = __fadd_rn(a01, __fmul_rn(Hs[p.y * HS + 32 + lane], pc));
                }
#pragma unroll 1
                for (int j = i; j < cnt1; j++) {
                    int2 q = __ldg(cs1 + j);
                    float qc = __int_as_float(q.x);
                    a10 = __fadd_rn(a10, __fmul_rn(Hs[q.y * HS + lane], qc));
                    if (COUTB == 64)
                        a11 = __fadd_rn(a11, __fmul_rn(Hs[q.y * HS + 32 + lane], qc));
                }
                {
                    float dvd = g_dinv[n0];
                    float sl2 = __fmul_rn(dvd, dvd);
                    float v = __fadd_rn(a00, __fmul_rn(Hs[d0 * HS + lane], sl2));
                    v = __fadd_rn(v, __ldg(&b[cb + lane]));
                    g_hcat[(size_t)n0 * 256 + outoff + cb + lane] = tanh_xla(v);
                    if (COUTB == 64) {
                        float w = __fadd_rn(a01, __fmul_rn(Hs[d0 * HS + 32 + lane], sl2));
                        w = __fadd_rn(w, __ldg(&b[cb + 32 + lane]));
                        g_hcat[(size_t)n0 * 256 + outoff + cb + 32 + lane] = tanh_xla(w);
                    }
                }
                {
                    float dvd = g_dinv[n1];
                    float sl2 = __fmul_rn(dvd, dvd);
                    float v = __fadd_rn(a10, __fmul_rn(Hs[d1 * HS + lane], sl2));
                    v = __fadd_rn(v, __ldg(&b[cb + lane]));
                    g_hcat[(size_t)n1 * 256 + outoff + cb + lane] = tanh_xla(v);
                    if (COUTB == 64) {
                        float w = __fadd_rn(a11, __fmul_rn(Hs[d1 * HS + 32 + lane], sl2));
                        w = __fadd_rn(w, __ldg(&b[cb + 32 + lane]));
                        g_hcat[(size_t)n1 * 256 + outoff + cb + 32 + lane] = tanh_xla(w);
                    }
                }
            }
        }
        __syncthreads();
    }
}

// ---------------- head phase (device func, same smem buffer) -------------------
#define TLS 257
__device__ __forceinline__ void head_phase(
    unsigned char* smraw,
    const float* __restrict__ W5, const float* __restrict__ b5,
    const float* __restrict__ W6, const float* __restrict__ b6,
    const float* __restrict__ Wf1, const float* __restrict__ bf1,
    const float* __restrict__ Wf2, const float* __restrict__ bf2,
    float* __restrict__ out)
{
    float* W5s    = (float*)smraw;                 // 4096 f  @0
    float* tile   = (float*)(smraw + 16384);       // 16*257  @16384
    float* z      = (float*)(smraw + 32832);       // 1024 f
    float* zp     = (float*)(smraw + 36928);       // 512 f
    float* y      = (float*)(smraw + 38976);       // 896 f
    float* f1     = (float*)(smraw + 42560);       // 128 f
    float* vals   = (float*)(smraw + 43072);       // 128 f
    int*   order  = (int*)(smraw + 43584);         // 64 i
    float* logits = (float*)(smraw + 43840);       // 10 f
    float* red    = (float*)(smraw + 43880);       // 2 f

    const int g = blockIdx.x, tid = threadIdx.x;
    const float* hrow = g_hcat + (size_t)g * 128 * 256;

    if (tid < 128) vals[tid] = hrow[tid * 256 + 255];
    for (int i = tid; i < 4096; i += 256) W5s[i] = W5[i];
    __syncthreads();

    if (tid < 128) {
        float v = vals[tid];
        int rank = 0;
        for (int j = 0; j < 128; j++) {
            float vj = vals[j];
            rank += (vj > v) || (vj == v && j < tid);
        }
        if (rank < 64) order[rank] = tid;
    }
    __syncthreads();

    {
        const int c = tid >> 4, tg = tid & 15;
        const float bc = b5[c];
#pragma unroll 1
        for (int tt = 0; tt < 4; tt++) {
            for (int idx = tid; idx < 16 * 256; idx += 256) {
                int r = idx >> 8, j = idx & 255;
                tile[r * TLS + j] = hrow[(size_t)order[tt * 16 + r] * 256 + j];
            }
            __syncthreads();
            float a0 = 0.f;
#pragma unroll 4
            for (int j = 0; j < 256; j++)
                a0 = fmaf(tile[tg * TLS + j], W5s[c * 256 + j], a0);
            z[c * 64 + tt * 16 + tg] = fmaxf(__fadd_rn(a0, bc), 0.f);
            __syncthreads();
        }
    }

    for (int idx = tid; idx < 512; idx += 256) {
        int c = idx >> 5, u = idx & 31;
        zp[c * 32 + u] = fmaxf(z[c * 64 + 2 * u], z[c * 64 + 2 * u + 1]);
    }
    __syncthreads();

    for (int idx = tid; idx < 896; idx += 256) {
        int o = idx / 28, t = idx - o * 28;
        float a0 = 0.f;
#pragma unroll
        for (int i = 0; i < 16; i++)
#pragma unroll
            for (int k = 0; k < 5; k++)
                a0 = fmaf(zp[i * 32 + t + k], __ldg(&W6[(o * 16 + i) * 5 + k]), a0);
        y[idx] = fmaxf(__fadd_rn(a0, b6[o]), 0.f);
    }
    __syncthreads();

    if (tid < 128) {
        float a0 = 0.f;
#pragma unroll 8
        for (int i = 0; i < 896; i++)
            a0 = fmaf(y[i], __ldg(&Wf1[(size_t)i * 128 + tid]), a0);
        f1[tid] = fmaxf(__fadd_rn(a0, bf1[tid]), 0.f);
    }
    __syncthreads();

    if (tid < 10) {
        float a0 = 0.f;
#pragma unroll 8
        for (int j = 0; j < 128; j++)
            a0 = fmaf(f1[j], __ldg(&Wf2[j * 10 + tid]), a0);
        logits[tid] = __fadd_rn(a0, bf2[tid]);
    }
    __syncthreads();
    if (tid == 0) {
        float m = logits[0];
        for (int k = 1; k < 10; k++) m = fmaxf(m, logits[k]);
        float s = 0.f;
        for (int k = 0; k < 10; k++) s += expf(logits[k] - m);
        red[0] = m;
        red[1] = logf(s);
    }
    __syncthreads();
    if (tid < 10) out[g * 10 + tid] = logits[tid] - red[0] - red[1];
}

// ---------------- the fused network kernel: one CTA per graph ------------------
__global__ __launch_bounds__(256) void k_fused(
    const float* __restrict__ x,
    const float* __restrict__ W1, const float* __restrict__ b1,
    const float* __restrict__ W2, const float* __restrict__ b2,
    const float* __restrict__ W3, const float* __restrict__ b3,
    const float* __restrict__ W4, const float* __restrict__ b4,
    const float* __restrict__ W5, const float* __restrict__ b5,
    const float* __restrict__ W6, const float* __restrict__ b6,
    const float* __restrict__ Wf1, const float* __restrict__ bf1,
    const float* __restrict__ Wf2, const float* __restrict__ bf2,
    float* __restrict__ out)
{
    __shared__ __align__(16) unsigned char smraw[45056];   // 44KB union

    gcn_phase<128, 128, 64>(smraw, x,      128, 0,   W1, b1, 0);
    __syncthreads();
    gcn_phase<128, 64, 64>(smraw, g_hcat,  256, 0,   W2, b2, 128);
    __syncthreads();
    gcn_phase<64, 32, 32>(smraw, g_hcat,   256, 128, W3, b3, 192);
    __syncthreads();
    gcn_phase<32, 32, 32>(smraw, g_hcat,   256, 192, W4, b4, 224);
    __syncthreads();
    head_phase(smraw, W5, b5, W6, b6, Wf1, bf1, Wf2, bf2, out);
}

// ---------------- launch --------------------------------------------------------
extern "C" void kernel_launch(void* const* d_in, const int* in_sizes, int n_in,
                              void* d_out, int out_size)
{
    const float* x   = (const float*)d_in[0];
    const float* W1  = (const float*)d_in[1];
    const float* b1  = (const float*)d_in[2];
    const float* W2  = (const float*)d_in[3];
    const float* b2  = (const float*)d_in[4];
    const float* W3  = (const float*)d_in[5];
    const float* b3  = (const float*)d_in[6];
    const float* W4  = (const float*)d_in[7];
    const float* b4  = (const float*)d_in[8];
    const float* W5  = (const float*)d_in[9];
    const float* b5  = (const float*)d_in[10];
    const float* W6  = (const float*)d_in[11];
    const float* b6  = (const float*)d_in[12];
    const float* Wf1 = (const float*)d_in[13];
    const float* bf1 = (const float*)d_in[14];
    const float* Wf2 = (const float*)d_in[15];
    const float* bf2 = (const float*)d_in[16];
    const int*   ei  = (const int*)d_in[17];
    const int* src = ei;
    const int* dst = ei + NEDGES;
    float* out = (float*)d_out;

    void* cntAddr = nullptr;
    cudaGetSymbolAddress(&cntAddr, g_cnt);
    cudaMemsetAsync(cntAddr, 0, NNODES * sizeof(unsigned));

    k_count_scatter<<<NEDGES / 256, 256>>>(src, dst);
    k_edges<<<NNODES / 128, 128>>>(src);
    k_fused<<<NG, 256>>>(x, W1, b1, W2, b2, W3, b3, W4, b4,
                         W5, b5, W6, b6, Wf1, bf1, Wf2, bf2, out);
}